// round 7
// baseline (speedup 1.0000x reference)
#include <cuda_runtime.h>
#include <cuda_bf16.h>
#include <math.h>
#include <stdint.h>

#define B_ROWS 8192
#define D_DIM  1024
#define NTHREADS_SCAN 1024

// ---------------- scratch (static device globals) ---------------------------
__device__ int   g_M;
__device__ int   g_sel[B_ROWS];
__device__ __align__(16) int g_lab[B_ROWS];
__device__ __align__(128) __nv_bfloat16 g_hi[(size_t)B_ROWS * D_DIM];   // 16 MB
__device__ __align__(128) uint8_t g_h8[(size_t)B_ROWS * D_DIM];         // 8 MB  e4m3(x)
__device__ __align__(128) uint8_t g_l8[(size_t)B_ROWS * D_DIM];         // 8 MB  e4m3(256*lo)
__device__ __align__(128) float g_sim[(size_t)B_ROWS * (size_t)B_ROWS];
__device__ float g_rowloss[B_ROWS];

__device__ __forceinline__ uint32_t smem_u32(const void* p) {
    uint32_t a;
    asm("{ .reg .u64 t; cvta.to.shared.u64 t, %1; cvt.u32.u64 %0, t; }" : "=r"(a) : "l"(p));
    return a;
}
// pack 2 floats -> e4m3x2 (lo byte = a, hi byte = b)
__device__ __forceinline__ uint16_t pack_e4m3x2(float a, float b) {
    uint16_t p;
    asm("cvt.rn.satfinite.e4m3x2.f32 %0, %1, %2;" : "=h"(p) : "f"(b), "f"(a));
    return p;
}

// ---------------- kernel 0: select + compaction ------------------------------
__global__ void __launch_bounds__(NTHREADS_SCAN)
k_select(const float* __restrict__ score, const void* __restrict__ labels_raw,
         const int* __restrict__ type_idx_p)
{
    const int t = threadIdx.x;
    __shared__ int s_is64;
    if (t == 0) {
        const int* L32 = (const int*)labels_raw;
        int z = 1;
        for (int k = 1; k < 128; k += 2) if (L32[k] != 0) { z = 0; break; }
        s_is64 = z;
    }
    __syncthreads();
    const int is64 = s_is64;
    const int ti = type_idx_p[0];

    float v[24];
    {
        const float4* s4p = (const float4*)score + 6 * t;
#pragma unroll
        for (int q = 0; q < 6; q++) {
            float4 x = __ldg(s4p + q);
            v[q * 4 + 0] = x.x; v[q * 4 + 1] = x.y; v[q * 4 + 2] = x.z; v[q * 4 + 3] = x.w;
        }
    }

    int flags[8], lab8[8], loc = 0;
#pragma unroll
    for (int q = 0; q < 8; q++) {
        int i = t * 8 + q;
        float s0 = v[3 * q], s1 = v[3 * q + 1], s2 = v[3 * q + 2];
        int am = 0; float b = s0;
        if (s1 > b) { b = s1; am = 1; }
        if (s2 > b) { b = s2; am = 2; }
        flags[q] = (am == ti) ? 1 : 0;
        if (is64) lab8[q] = (int)(((const long long*)labels_raw)[i]);
        else      lab8[q] = ((const int*)labels_raw)[i];
        loc += flags[q];
    }

    __shared__ int sc[NTHREADS_SCAN];
    sc[t] = loc;
    __syncthreads();
    for (int off = 1; off < NTHREADS_SCAN; off <<= 1) {
        int x = (t >= off) ? sc[t - off] : 0;
        __syncthreads();
        sc[t] += x;
        __syncthreads();
    }
    int incl = sc[t];
    int pos = incl - loc;
#pragma unroll
    for (int q = 0; q < 8; q++) {
        int i = t * 8 + q;
        if (flags[q]) { g_sel[pos] = i; g_lab[pos] = lab8[q]; pos++; }
    }
    if (t == NTHREADS_SCAN - 1) g_M = incl;
}

// ---------------- kernel 1: gather + normalize + bf16 hi / fp8 h8,l8 ---------
__global__ void __launch_bounds__(256)
k_normalize(const float* __restrict__ feats)
{
    const int j = blockIdx.x;
    const int M = g_M;
    const int Mpad = (M + 127) & ~127;
    if (j >= Mpad) return;
    const int t = threadIdx.x;

    if (j >= M) {   // zero pad rows + sentinel label
        ((uint2*)(g_hi + (size_t)j * D_DIM))[t] = make_uint2(0, 0);
        ((uint32_t*)(g_h8 + (size_t)j * D_DIM))[t] = 0;
        ((uint32_t*)(g_l8 + (size_t)j * D_DIM))[t] = 0;
        if (t == 0) g_lab[j] = 0x80000000;
        return;
    }
    const int src = g_sel[j];
    const float4 a = ((const float4*)(feats + (size_t)src * D_DIM))[t];
    float ss = a.x * a.x + a.y * a.y + a.z * a.z + a.w * a.w;

    __shared__ float red[256];
    red[t] = ss;
    __syncthreads();
    for (int off = 128; off > 0; off >>= 1) {
        if (t < off) red[t] += red[t + off];
        __syncthreads();
    }
    const float inv = 1.0f / fmaxf(sqrtf(red[0]), 1e-12f);

    float o[4] = { a.x * inv, a.y * inv, a.z * inv, a.w * inv };
    __nv_bfloat16 h[4];
    float lo[4];
#pragma unroll
    for (int q = 0; q < 4; q++) {
        h[q] = __float2bfloat16_rn(o[q]);
        lo[q] = (o[q] - __bfloat162float(h[q])) * 256.0f;
    }
    uint2 hp;
    hp.x = (uint32_t)(*(uint16_t*)&h[0]) | ((uint32_t)(*(uint16_t*)&h[1]) << 16);
    hp.y = (uint32_t)(*(uint16_t*)&h[2]) | ((uint32_t)(*(uint16_t*)&h[3]) << 16);
    ((uint2*)(g_hi + (size_t)j * D_DIM))[t] = hp;

    const uint32_t h8w = (uint32_t)pack_e4m3x2(o[0], o[1]) |
                         ((uint32_t)pack_e4m3x2(o[2], o[3]) << 16);
    const uint32_t l8w = (uint32_t)pack_e4m3x2(lo[0], lo[1]) |
                         ((uint32_t)pack_e4m3x2(lo[2], lo[3]) << 16);
    ((uint32_t*)(g_h8 + (size_t)j * D_DIM))[t] = h8w;
    ((uint32_t*)(g_l8 + (size_t)j * D_DIM))[t] = l8w;
}

// ---------------- kernel 2: bf16 hi*hi + fp8 corrections GEMM ---------------
#define TILE 128
#define KC 64                                 // bf16 elems per 128B row chunk
#define NCH1 16                               // bf16 chunks (K=1024)
#define NCH2 8                                // fp8 chunks (K=128 each)
#define NCHT (NCH1 + NCH2)                    // 24
#define TILE_BYTES (TILE * 128)               // 16384
#define STAGE_BYTES (4 * TILE_BYTES)          // 65536
#define NSTAGE 3
#define GEMM_SMEM (NSTAGE * STAGE_BYTES)      // 196608
#define PAD_SENTINEL -1e30f
#define INV256 (1.0f / 256.0f)

__device__ __forceinline__ void ldsm4(uint32_t* r, uint32_t addr) {
    asm volatile("ldmatrix.sync.aligned.m8n8.x4.shared.b16 {%0,%1,%2,%3}, [%4];"
                 : "=r"(r[0]), "=r"(r[1]), "=r"(r[2]), "=r"(r[3]) : "r"(addr));
}
__device__ __forceinline__ void mma16816(float* d, const uint32_t* a, const uint32_t* b) {
    asm volatile(
        "mma.sync.aligned.m16n8k16.row.col.f32.bf16.bf16.f32 "
        "{%0,%1,%2,%3}, {%4,%5,%6,%7}, {%8,%9}, {%0,%1,%2,%3};"
        : "+f"(d[0]), "+f"(d[1]), "+f"(d[2]), "+f"(d[3])
        : "r"(a[0]), "r"(a[1]), "r"(a[2]), "r"(a[3]), "r"(b[0]), "r"(b[1]));
}
__device__ __forceinline__ void mma16832f8(float* d, const uint32_t* a, const uint32_t* b) {
    asm volatile(
        "mma.sync.aligned.m16n8k32.row.col.f32.e4m3.e4m3.f32 "
        "{%0,%1,%2,%3}, {%4,%5,%6,%7}, {%8,%9}, {%0,%1,%2,%3};"
        : "+f"(d[0]), "+f"(d[1]), "+f"(d[2]), "+f"(d[3])
        : "r"(a[0]), "r"(a[1]), "r"(a[2]), "r"(a[3]), "r"(b[0]), "r"(b[1]));
}

__global__ void __launch_bounds__(256, 1)
k_gemm()
{
    const int M = g_M;
    const int tiles = (M + 127) >> 7;
    const int bx = blockIdx.x, by = blockIdx.y;
    if (by >= tiles || bx > by) return;        // lower-triangle tiles only
    const int ldm = tiles << 7;
    const int rt = by * TILE;
    const int ct = bx * TILE;
    const int tid = threadIdx.x;
    const int lane = tid & 31;
    const int wid = tid >> 5;
    const int wm = wid >> 1;
    const int wn = wid & 1;

    extern __shared__ __align__(1024) char smc[];
    const uint32_t tb = smem_u32(smc);

    // loader: chunk < NCH1 -> bf16 hi tiles (A,B); else fp8 tiles (Ah8,Bh8,Al8,Bl8)
    auto load_chunk = [&](int k, int stage) {
        const uint32_t sb = tb + stage * STAGE_BYTES;
        if (k < NCH1) {
            const int kb = k * KC;
#pragma unroll
            for (int i = 0; i < 8; i++) {
                const int c = tid + i * 256;   // 0..2047
                const int tix = c >> 10;       // 0..1 : A_hi, B_hi
                const int r   = (c >> 3) & 127;
                const int seg = c & 7;
                const __nv_bfloat16* src = g_hi + (size_t)((tix ? ct : rt) + r) * D_DIM + kb + seg * 8;
                uint32_t dst = sb + tix * TILE_BYTES + r * 128 + ((seg ^ (r & 7)) << 4);
                asm volatile("cp.async.cg.shared.global [%0], [%1], 16;" :: "r"(dst), "l"(src));
            }
        } else {
            const int kb = (k - NCH1) * 128;   // fp8 elems per chunk = 128
#pragma unroll
            for (int i = 0; i < 16; i++) {
                const int c = tid + i * 256;   // 0..4095
                const int tix = c >> 10;       // 0:Ah8 1:Bh8 2:Al8 3:Bl8
                const int r   = (c >> 3) & 127;
                const int seg = c & 7;
                const uint8_t* base = (tix >= 2) ? g_l8 : g_h8;
                const uint8_t* src = base + (size_t)(((tix & 1) ? ct : rt) + r) * D_DIM + kb + seg * 16;
                uint32_t dst = sb + tix * TILE_BYTES + r * 128 + ((seg ^ (r & 7)) << 4);
                asm volatile("cp.async.cg.shared.global [%0], [%1], 16;" :: "r"(dst), "l"(src));
            }
        }
        asm volatile("cp.async.commit_group;");
    };

    float acc[2][8][4];
#pragma unroll
    for (int mf = 0; mf < 2; mf++)
#pragma unroll
        for (int nf = 0; nf < 8; nf++)
#pragma unroll
            for (int i = 0; i < 4; i++) acc[mf][nf][i] = 0.0f;

    load_chunk(0, 0);
    load_chunk(1, 1);
    load_chunk(2, 2);

    for (int k = 0; k < NCHT; k++) {
        if (k + 3 <= NCHT)      asm volatile("cp.async.wait_group 2;" ::: "memory");
        else if (k + 2 == NCHT) asm volatile("cp.async.wait_group 1;" ::: "memory");
        else                    asm volatile("cp.async.wait_group 0;" ::: "memory");
        __syncthreads();

        const int st = k % NSTAGE;
        const uint32_t sb = tb + st * STAGE_BYTES;

        if (k < NCH1) {
            // ---- bf16 hi*hi ----
            const uint32_t Ahi = sb;
            const uint32_t Bhi = sb + TILE_BYTES;
#pragma unroll
            for (int ks = 0; ks < 4; ks++) {
                uint32_t ah[2][4];
#pragma unroll
                for (int mf = 0; mf < 2; mf++) {
                    const int row = wm * 32 + mf * 16 + (lane & 15);
                    const int seg = ks * 2 + (lane >> 4);
                    ldsm4(ah[mf], Ahi + row * 128 + ((seg ^ (row & 7)) << 4));
                }
                uint32_t bh[4][4];
#pragma unroll
                for (int nq = 0; nq < 4; nq++) {
                    const int row = wn * 64 + nq * 16 + (lane & 7) + ((lane >> 4) << 3);
                    const int seg = ks * 2 + ((lane >> 3) & 1);
                    ldsm4(bh[nq], Bhi + row * 128 + ((seg ^ (row & 7)) << 4));
                }
#pragma unroll
                for (int mf = 0; mf < 2; mf++)
#pragma unroll
                    for (int nf = 0; nf < 8; nf++)
                        mma16816(acc[mf][nf], ah[mf], &bh[nf >> 1][(nf & 1) * 2]);
            }
            if (k == NCH1 - 1) {   // rescale: subsequent fp8 products carry 256x
#pragma unroll
                for (int mf = 0; mf < 2; mf++)
#pragma unroll
                    for (int nf = 0; nf < 8; nf++)
#pragma unroll
                        for (int i = 0; i < 4; i++) acc[mf][nf][i] *= 256.0f;
            }
        } else {
            // ---- fp8 corrections: h8*l8 + l8*h8 (k32 steps, same frag bytes) ----
            const uint32_t Ah8 = sb;
            const uint32_t Bh8 = sb + TILE_BYTES;
            const uint32_t Al8 = sb + 2 * TILE_BYTES;
            const uint32_t Bl8 = sb + 3 * TILE_BYTES;
#pragma unroll
            for (int ks = 0; ks < 4; ks++) {
                uint32_t a8h[2][4], a8l[2][4];
#pragma unroll
                for (int mf = 0; mf < 2; mf++) {
                    const int row = wm * 32 + mf * 16 + (lane & 15);
                    const int seg = ks * 2 + (lane >> 4);
                    const uint32_t off = row * 128 + ((seg ^ (row & 7)) << 4);
                    ldsm4(a8h[mf], Ah8 + off);
                    ldsm4(a8l[mf], Al8 + off);
                }
                uint32_t b8h[4][4], b8l[4][4];
#pragma unroll
                for (int nq = 0; nq < 4; nq++) {
                    const int row = wn * 64 + nq * 16 + (lane & 7) + ((lane >> 4) << 3);
                    const int seg = ks * 2 + ((lane >> 3) & 1);
                    const uint32_t off = row * 128 + ((seg ^ (row & 7)) << 4);
                    ldsm4(b8h[nq], Bh8 + off);
                    ldsm4(b8l[nq], Bl8 + off);
                }
#pragma unroll
                for (int mf = 0; mf < 2; mf++)
#pragma unroll
                    for (int nf = 0; nf < 8; nf++)
                        mma16832f8(acc[mf][nf], a8h[mf], &b8l[nf >> 1][(nf & 1) * 2]);
#pragma unroll
                for (int mf = 0; mf < 2; mf++)
#pragma unroll
                    for (int nf = 0; nf < 8; nf++)
                        mma16832f8(acc[mf][nf], a8l[mf], &b8h[nf >> 1][(nf & 1) * 2]);
            }
        }
        __syncthreads();
        if (k + 3 < NCHT) load_chunk(k + 3, st);
    }

    // ---- epilogue: scale 1/256, pad sentinels, direct stores ----
#pragma unroll
    for (int mf = 0; mf < 2; mf++)
#pragma unroll
        for (int nf = 0; nf < 8; nf++) {
#pragma unroll
            for (int i = 0; i < 4; i++) acc[mf][nf][i] *= INV256;
            const int r0 = rt + wm * 32 + mf * 16 + (lane >> 2);
            const int c0 = ct + wn * 64 + nf * 8 + (lane & 3) * 2;
            float v0 = (c0     >= M) ? PAD_SENTINEL : acc[mf][nf][0];
            float v1 = (c0 + 1 >= M) ? PAD_SENTINEL : acc[mf][nf][1];
            float v2 = (c0     >= M) ? PAD_SENTINEL : acc[mf][nf][2];
            float v3 = (c0 + 1 >= M) ? PAD_SENTINEL : acc[mf][nf][3];
            *(float2*)(g_sim + (size_t)r0 * ldm + c0)       = make_float2(v0, v1);
            *(float2*)(g_sim + (size_t)(r0 + 8) * ldm + c0) = make_float2(v2, v3);
        }

    if (bx == by) {
        __syncthreads();
        if (tid < 128) {
            const int d = rt + tid;
            if (d < M) g_sim[(size_t)d * ldm + d] = 1.0f;
        }
    } else {
        float* S = (float*)smc;      // [128][136]
#pragma unroll
        for (int mf = 0; mf < 2; mf++)
#pragma unroll
            for (int nf = 0; nf < 8; nf++) {
                const int rl = wm * 32 + mf * 16 + (lane >> 2);
                const int cl = wn * 64 + nf * 8 + (lane & 3) * 2;
                S[cl * 136 + rl]           = acc[mf][nf][0];
                S[(cl + 1) * 136 + rl]     = acc[mf][nf][1];
                S[cl * 136 + rl + 8]       = acc[mf][nf][2];
                S[(cl + 1) * 136 + rl + 8] = acc[mf][nf][3];
            }
        __syncthreads();
        for (int i = tid; i < 128 * 32; i += 256) {
            const int row = i >> 5;
            const int c4  = (i & 31) * 4;
            float4 v = make_float4(S[row * 136 + c4], S[row * 136 + c4 + 1],
                                   S[row * 136 + c4 + 2], S[row * 136 + c4 + 3]);
            if (rt + c4     >= M) v.x = PAD_SENTINEL;
            if (rt + c4 + 1 >= M) v.y = PAD_SENTINEL;
            if (rt + c4 + 2 >= M) v.z = PAD_SENTINEL;
            if (rt + c4 + 3 >= M) v.w = PAD_SENTINEL;
            *(float4*)(g_sim + (size_t)(ct + row) * ldm + rt + c4) = v;
        }
    }
}

// ---------------- kernel 3: per-row epilogue (R5 measured-best version) ------
#define RL_CAP 4096

__global__ void __launch_bounds__(256)
k_rowloss()
{
    const int r = blockIdx.x;
    const int M = g_M;
    if (r >= M) return;
    const int Mpad = (M + 127) & ~127;
    const int t = threadIdx.x;
    const int lane = t & 31;
    const int w = t >> 5;
    const int labr = __ldg(&g_lab[r]);
    const float4* __restrict__ row4 = (const float4*)(g_sim + (size_t)r * (size_t)Mpad);
    const int4* __restrict__ lab4 = (const int4*)g_lab;
    const float INF = __int_as_float(0x7f800000);
    const float C1 = 1.0f - 1e-5f;
    const bool use_smem = (Mpad <= RL_CAP);

    __shared__ float ss[RL_CAP];
    __shared__ unsigned char se[RL_CAP];
    __shared__ float w_min[8], w_max[8], w_p[8], w_n[8];
    __shared__ int w_cnt[8];

    float minpos = INF, maxneg = -INF;
    int cnt = 0;
    const int Mpad4 = Mpad >> 2;
    for (int q = t; q < Mpad4; q += 256) {
        const float4 sv = __ldg(row4 + q);
        const int4 lv = __ldg(lab4 + q);
        const float s4[4] = { sv.x, sv.y, sv.z, sv.w };
        const int l4[4] = { lv.x, lv.y, lv.z, lv.w };
#pragma unroll
        for (int e = 0; e < 4; e++) {
            const int j = q * 4 + e;
            float sval = -1e30f;
            unsigned char eqv = 0;
            if (j < M) {
                const float s = (j == r) ? 1.0f : s4[e];
                const bool eq = (l4[e] == labr);
                sval = s; eqv = eq ? 1 : 0;
                if (eq) { cnt++; if (s < C1) minpos = fminf(minpos, s); }
                else maxneg = fmaxf(maxneg, s);
            }
            if (use_smem) { ss[j] = sval; se[j] = eqv; }
        }
    }
#pragma unroll
    for (int o = 16; o; o >>= 1) {
        minpos = fminf(minpos, __shfl_xor_sync(0xffffffffu, minpos, o));
        maxneg = fmaxf(maxneg, __shfl_xor_sync(0xffffffffu, maxneg, o));
        cnt += __shfl_xor_sync(0xffffffffu, cnt, o);
    }
    if (lane == 0) { w_min[w] = minpos; w_max[w] = maxneg; w_cnt[w] = cnt; }
    __syncthreads();
    float mp = INF, mn = -INF;
    int c = 0;
#pragma unroll
    for (int q = 0; q < 8; q++) { mp = fminf(mp, w_min[q]); mn = fmaxf(mn, w_max[q]); c += w_cnt[q]; }

    const bool valid = (c > 1) && (mp < INF) && (mn > -INF) && (mn > mp - 0.1f);
    if (!valid) {
        if (t == 0) g_rowloss[r] = 0.0f;
        return;
    }

    float psum = 0.f, nsum = 0.f;
    if (use_smem) {
        for (int j = t; j < Mpad; j += 256) {
            const float s = ss[j];
            if (!se[j]) {
                if (s + 0.1f > mp) nsum += __expf(40.0f * (s - 0.5f));
            } else if (s < C1 && s - 0.1f < mn) {
                psum += __expf(-2.0f * (s - 0.5f));
            }
        }
    } else {
        const float* __restrict__ row = (const float*)row4;
        for (int j = t; j < M; j += 256) {
            const float s = (j == r) ? 1.0f : __ldg(row + j);
            const bool eq = (__ldg(&g_lab[j]) == labr);
            if (!eq) {
                if (s + 0.1f > mp) nsum += __expf(40.0f * (s - 0.5f));
            } else if (s < C1 && s - 0.1f < mn) {
                psum += __expf(-2.0f * (s - 0.5f));
            }
        }
    }
#pragma unroll
    for (int o = 16; o; o >>= 1) {
        psum += __shfl_xor_sync(0xffffffffu, psum, o);
        nsum += __shfl_xor_sync(0xffffffffu, nsum, o);
    }
    if (lane == 0) { w_p[w] = psum; w_n[w] = nsum; }
    __syncthreads();
    if (t == 0) {
        float P = 0.f, N = 0.f;
#pragma unroll
        for (int q = 0; q < 8; q++) { P += w_p[q]; N += w_n[q]; }
        g_rowloss[r] = log1pf(P) / 2.0f + log1pf(N) / 40.0f;
    }
}

// ---------------- kernel 4: deterministic final sum --------------------------
__global__ void __launch_bounds__(256)
k_finalize(float* __restrict__ out)
{
    const int M = g_M;
    const int t = threadIdx.x;
    float acc = 0.f;
    for (int i = t; i < M; i += 256) acc += g_rowloss[i];
    __shared__ float red[256];
    red[t] = acc;
    __syncthreads();
    for (int off = 128; off > 0; off >>= 1) {
        if (t < off) red[t] += red[t + off];
        __syncthreads();
    }
    if (t == 0) out[0] = red[0] / (float)B_ROWS;
}

// ---------------- launcher ---------------------------------------------------
extern "C" void kernel_launch(void* const* d_in, const int* in_sizes, int n_in,
                              void* d_out, int out_size)
{
    const float* feats  = (const float*)d_in[0];
    const void*  labels = d_in[1];
    const float* score  = (const float*)d_in[2];
    const int*   tidx   = (const int*)d_in[3];
    float* out = (float*)d_out;

    cudaFuncSetAttribute(k_gemm, cudaFuncAttributeMaxDynamicSharedMemorySize, GEMM_SMEM);

    k_select<<<1, NTHREADS_SCAN>>>(score, labels, tidx);
    k_normalize<<<B_ROWS, 256>>>(feats);
    dim3 grid(B_ROWS / TILE, B_ROWS / TILE);
    k_gemm<<<grid, 256, GEMM_SMEM>>>();
    k_rowloss<<<B_ROWS, 256>>>();
    k_finalize<<<1, 256>>>(out);
}

// round 8
// speedup vs baseline: 1.9302x; 1.9302x over previous
#include <cuda_runtime.h>
#include <cuda_fp16.h>
#include <math.h>
#include <stdint.h>

#define B_ROWS 8192
#define D_DIM  1024
#define NTHREADS_SCAN 1024

// ---------------- scratch (static device globals) ---------------------------
__device__ int   g_M;
__device__ int   g_sel[B_ROWS];
__device__ __align__(16) int g_lab[B_ROWS];
__device__ __align__(128) __half g_f16[(size_t)B_ROWS * D_DIM];         // 16 MB
__device__ __align__(128) float g_sim[(size_t)B_ROWS * (size_t)B_ROWS];
__device__ float g_rowloss[B_ROWS];

__device__ __forceinline__ uint32_t smem_u32(const void* p) {
    uint32_t a;
    asm("{ .reg .u64 t; cvta.to.shared.u64 t, %1; cvt.u32.u64 %0, t; }" : "=r"(a) : "l"(p));
    return a;
}

// ---------------- kernel 0: select + compaction ------------------------------
__global__ void __launch_bounds__(NTHREADS_SCAN)
k_select(const float* __restrict__ score, const void* __restrict__ labels_raw,
         const int* __restrict__ type_idx_p)
{
    const int t = threadIdx.x;
    __shared__ int s_is64;
    if (t == 0) {
        const int* L32 = (const int*)labels_raw;
        int z = 1;
        for (int k = 1; k < 128; k += 2) if (L32[k] != 0) { z = 0; break; }
        s_is64 = z;
    }
    __syncthreads();
    const int is64 = s_is64;
    const int ti = type_idx_p[0];

    float v[24];
    {
        const float4* s4p = (const float4*)score + 6 * t;
#pragma unroll
        for (int q = 0; q < 6; q++) {
            float4 x = __ldg(s4p + q);
            v[q * 4 + 0] = x.x; v[q * 4 + 1] = x.y; v[q * 4 + 2] = x.z; v[q * 4 + 3] = x.w;
        }
    }

    int flags[8], lab8[8], loc = 0;
#pragma unroll
    for (int q = 0; q < 8; q++) {
        int i = t * 8 + q;
        float s0 = v[3 * q], s1 = v[3 * q + 1], s2 = v[3 * q + 2];
        int am = 0; float b = s0;
        if (s1 > b) { b = s1; am = 1; }
        if (s2 > b) { b = s2; am = 2; }
        flags[q] = (am == ti) ? 1 : 0;
        if (is64) lab8[q] = (int)(((const long long*)labels_raw)[i]);
        else      lab8[q] = ((const int*)labels_raw)[i];
        loc += flags[q];
    }

    __shared__ int sc[NTHREADS_SCAN];
    sc[t] = loc;
    __syncthreads();
    for (int off = 1; off < NTHREADS_SCAN; off <<= 1) {
        int x = (t >= off) ? sc[t - off] : 0;
        __syncthreads();
        sc[t] += x;
        __syncthreads();
    }
    int incl = sc[t];
    int pos = incl - loc;
#pragma unroll
    for (int q = 0; q < 8; q++) {
        int i = t * 8 + q;
        if (flags[q]) { g_sel[pos] = i; g_lab[pos] = lab8[q]; pos++; }
    }
    if (t == NTHREADS_SCAN - 1) g_M = incl;
}

// ---------------- kernel 1: gather + L2 normalize + fp16 ---------------------
__global__ void __launch_bounds__(256)
k_normalize(const float* __restrict__ feats)
{
    const int j = blockIdx.x;
    const int M = g_M;
    const int Mpad = (M + 127) & ~127;
    if (j >= Mpad) return;
    const int t = threadIdx.x;

    if (j >= M) {   // zero pad rows + sentinel label
        ((uint2*)(g_f16 + (size_t)j * D_DIM))[t] = make_uint2(0, 0);
        if (t == 0) g_lab[j] = 0x80000000;
        return;
    }
    const int src = g_sel[j];
    const float4 a = ((const float4*)(feats + (size_t)src * D_DIM))[t];
    float ss = a.x * a.x + a.y * a.y + a.z * a.z + a.w * a.w;

    __shared__ float red[256];
    red[t] = ss;
    __syncthreads();
    for (int off = 128; off > 0; off >>= 1) {
        if (t < off) red[t] += red[t + off];
        __syncthreads();
    }
    const float inv = 1.0f / fmaxf(sqrtf(red[0]), 1e-12f);

    __half h[4];
    h[0] = __float2half_rn(a.x * inv);
    h[1] = __float2half_rn(a.y * inv);
    h[2] = __float2half_rn(a.z * inv);
    h[3] = __float2half_rn(a.w * inv);
    uint2 hp;
    hp.x = (uint32_t)(*(uint16_t*)&h[0]) | ((uint32_t)(*(uint16_t*)&h[1]) << 16);
    hp.y = (uint32_t)(*(uint16_t*)&h[2]) | ((uint32_t)(*(uint16_t*)&h[3]) << 16);
    ((uint2*)(g_f16 + (size_t)j * D_DIM))[t] = hp;
}

// ---------------- kernel 2: fp16 single-product GEMM (symmetric tiles) -------
#define TILE 128
#define KC 64
#define NCHUNK (D_DIM / KC)                   // 16
#define TILE_BYTES (TILE * 128)               // 16384
#define STAGE_BYTES (2 * TILE_BYTES)          // 32768 (A,B)
#define NSTAGE 3
#define GEMM_SMEM (NSTAGE * STAGE_BYTES)      // 98304 -> 2 CTAs/SM
#define PAD_SENTINEL -1e30f

__device__ __forceinline__ void ldsm4(uint32_t* r, uint32_t addr) {
    asm volatile("ldmatrix.sync.aligned.m8n8.x4.shared.b16 {%0,%1,%2,%3}, [%4];"
                 : "=r"(r[0]), "=r"(r[1]), "=r"(r[2]), "=r"(r[3]) : "r"(addr));
}
__device__ __forceinline__ void mma16816h(float* d, const uint32_t* a, const uint32_t* b) {
    asm volatile(
        "mma.sync.aligned.m16n8k16.row.col.f32.f16.f16.f32 "
        "{%0,%1,%2,%3}, {%4,%5,%6,%7}, {%8,%9}, {%0,%1,%2,%3};"
        : "+f"(d[0]), "+f"(d[1]), "+f"(d[2]), "+f"(d[3])
        : "r"(a[0]), "r"(a[1]), "r"(a[2]), "r"(a[3]), "r"(b[0]), "r"(b[1]));
}

__global__ void __launch_bounds__(256, 2)
k_gemm()
{
    const int M = g_M;
    const int tiles = (M + 127) >> 7;
    const int bx = blockIdx.x, by = blockIdx.y;
    if (by >= tiles || bx > by) return;        // lower-triangle tiles only
    const int ldm = tiles << 7;
    const int rt = by * TILE;
    const int ct = bx * TILE;
    const int tid = threadIdx.x;
    const int lane = tid & 31;
    const int wid = tid >> 5;
    const int wm = wid >> 1;
    const int wn = wid & 1;

    extern __shared__ __align__(1024) char smc[];
    const uint32_t tb = smem_u32(smc);

    // chunk loader: 2 tiles (A, B), 16B cp.async each: 2048 segs / 256 thr = 8
    auto load_chunk = [&](int kc, int stage) {
        const uint32_t sb = tb + stage * STAGE_BYTES;
        const int kb = kc * KC;
#pragma unroll
        for (int i = 0; i < 8; i++) {
            const int c = tid + i * 256;       // 0..2047
            const int tix = c >> 10;           // 0:A 1:B
            const int r   = (c >> 3) & 127;
            const int seg = c & 7;
            const __half* src = g_f16 + (size_t)((tix ? ct : rt) + r) * D_DIM + kb + seg * 8;
            uint32_t dst = sb + tix * TILE_BYTES + r * 128 + ((seg ^ (r & 7)) << 4);
            asm volatile("cp.async.cg.shared.global [%0], [%1], 16;" :: "r"(dst), "l"(src));
        }
        asm volatile("cp.async.commit_group;");
    };

    float acc[2][8][4];
#pragma unroll
    for (int mf = 0; mf < 2; mf++)
#pragma unroll
        for (int nf = 0; nf < 8; nf++)
#pragma unroll
            for (int i = 0; i < 4; i++) acc[mf][nf][i] = 0.0f;

    load_chunk(0, 0);
    load_chunk(1, 1);
    load_chunk(2, 2);

    for (int k = 0; k < NCHUNK; k++) {
        if (k + 3 <= NCHUNK)      asm volatile("cp.async.wait_group 2;" ::: "memory");
        else if (k + 2 == NCHUNK) asm volatile("cp.async.wait_group 1;" ::: "memory");
        else                      asm volatile("cp.async.wait_group 0;" ::: "memory");
        __syncthreads();

        const int st = k % NSTAGE;
        const uint32_t A = tb + st * STAGE_BYTES;
        const uint32_t B = A + TILE_BYTES;

#pragma unroll
        for (int ks = 0; ks < 4; ks++) {
            uint32_t ah[2][4];
#pragma unroll
            for (int mf = 0; mf < 2; mf++) {
                const int row = wm * 32 + mf * 16 + (lane & 15);
                const int seg = ks * 2 + (lane >> 4);
                ldsm4(ah[mf], A + row * 128 + ((seg ^ (row & 7)) << 4));
            }
            uint32_t bh[4][4];
#pragma unroll
            for (int nq = 0; nq < 4; nq++) {
                const int row = wn * 64 + nq * 16 + (lane & 7) + ((lane >> 4) << 3);
                const int seg = ks * 2 + ((lane >> 3) & 1);
                ldsm4(bh[nq], B + row * 128 + ((seg ^ (row & 7)) << 4));
            }
#pragma unroll
            for (int mf = 0; mf < 2; mf++)
#pragma unroll
                for (int nf = 0; nf < 8; nf++)
                    mma16816h(acc[mf][nf], ah[mf], &bh[nf >> 1][(nf & 1) * 2]);
        }
        __syncthreads();
        if (k + 3 < NCHUNK) load_chunk(k + 3, st);
    }

    // ---- epilogue: pad-column sentinels + direct stores ----
#pragma unroll
    for (int mf = 0; mf < 2; mf++)
#pragma unroll
        for (int nf = 0; nf < 8; nf++) {
            const int r0 = rt + wm * 32 + mf * 16 + (lane >> 2);
            const int c0 = ct + wn * 64 + nf * 8 + (lane & 3) * 2;
            float v0 = (c0     >= M) ? PAD_SENTINEL : acc[mf][nf][0];
            float v1 = (c0 + 1 >= M) ? PAD_SENTINEL : acc[mf][nf][1];
            float v2 = (c0     >= M) ? PAD_SENTINEL : acc[mf][nf][2];
            float v3 = (c0 + 1 >= M) ? PAD_SENTINEL : acc[mf][nf][3];
            *(float2*)(g_sim + (size_t)r0 * ldm + c0)       = make_float2(v0, v1);
            *(float2*)(g_sim + (size_t)(r0 + 8) * ldm + c0) = make_float2(v2, v3);
        }

    if (bx == by) {
        // exact diagonal = 1.0 (replicates reference's <1-eps self exclusion)
        __syncthreads();
        if (tid < 128) {
            const int d = rt + tid;
            if (d < M) g_sim[(size_t)d * ldm + d] = 1.0f;
        }
    } else {
        // mirror (transpose via SMEM); source pad rows -> sentinel cols
        float* S = (float*)smc;      // [128][136] = 69.6 KB, fits 96 KB
#pragma unroll
        for (int mf = 0; mf < 2; mf++)
#pragma unroll
            for (int nf = 0; nf < 8; nf++) {
                const int rl = wm * 32 + mf * 16 + (lane >> 2);
                const int cl = wn * 64 + nf * 8 + (lane & 3) * 2;
                S[cl * 136 + rl]           = acc[mf][nf][0];
                S[(cl + 1) * 136 + rl]     = acc[mf][nf][1];
                S[cl * 136 + rl + 8]       = acc[mf][nf][2];
                S[(cl + 1) * 136 + rl + 8] = acc[mf][nf][3];
            }
        __syncthreads();
        for (int i = tid; i < 128 * 32; i += 256) {
            const int row = i >> 5;
            const int c4  = (i & 31) * 4;
            float4 v = make_float4(S[row * 136 + c4], S[row * 136 + c4 + 1],
                                   S[row * 136 + c4 + 2], S[row * 136 + c4 + 3]);
            if (rt + c4     >= M) v.x = PAD_SENTINEL;
            if (rt + c4 + 1 >= M) v.y = PAD_SENTINEL;
            if (rt + c4 + 2 >= M) v.z = PAD_SENTINEL;
            if (rt + c4 + 3 >= M) v.w = PAD_SENTINEL;
            *(float4*)(g_sim + (size_t)(ct + row) * ldm + rt + c4) = v;
        }
    }
}

// ---------------- kernel 3: per-row epilogue (R5 measured-best) --------------
#define RL_CAP 4096

__global__ void __launch_bounds__(256)
k_rowloss()
{
    const int r = blockIdx.x;
    const int M = g_M;
    if (r >= M) return;
    const int Mpad = (M + 127) & ~127;
    const int t = threadIdx.x;
    const int lane = t & 31;
    const int w = t >> 5;
    const int labr = __ldg(&g_lab[r]);
    const float4* __restrict__ row4 = (const float4*)(g_sim + (size_t)r * (size_t)Mpad);
    const int4* __restrict__ lab4 = (const int4*)g_lab;
    const float INF = __int_as_float(0x7f800000);
    const float C1 = 1.0f - 1e-5f;
    const bool use_smem = (Mpad <= RL_CAP);

    __shared__ float ss[RL_CAP];
    __shared__ unsigned char se[RL_CAP];
    __shared__ float w_min[8], w_max[8], w_p[8], w_n[8];
    __shared__ int w_cnt[8];

    float minpos = INF, maxneg = -INF;
    int cnt = 0;
    const int Mpad4 = Mpad >> 2;
    for (int q = t; q < Mpad4; q += 256) {
        const float4 sv = __ldg(row4 + q);
        const int4 lv = __ldg(lab4 + q);
        const float s4[4] = { sv.x, sv.y, sv.z, sv.w };
        const int l4[4] = { lv.x, lv.y, lv.z, lv.w };
#pragma unroll
        for (int e = 0; e < 4; e++) {
            const int j = q * 4 + e;
            float sval = -1e30f;
            unsigned char eqv = 0;
            if (j < M) {
                const float s = (j == r) ? 1.0f : s4[e];
                const bool eq = (l4[e] == labr);
                sval = s; eqv = eq ? 1 : 0;
                if (eq) { cnt++; if (s < C1) minpos = fminf(minpos, s); }
                else maxneg = fmaxf(maxneg, s);
            }
            if (use_smem) { ss[j] = sval; se[j] = eqv; }
        }
    }
#pragma unroll
    for (int o = 16; o; o >>= 1) {
        minpos = fminf(minpos, __shfl_xor_sync(0xffffffffu, minpos, o));
        maxneg = fmaxf(maxneg, __shfl_xor_sync(0xffffffffu, maxneg, o));
        cnt += __shfl_xor_sync(0xffffffffu, cnt, o);
    }
    if (lane == 0) { w_min[w] = minpos; w_max[w] = maxneg; w_cnt[w] = cnt; }
    __syncthreads();
    float mp = INF, mn = -INF;
    int c = 0;
#pragma unroll
    for (int q = 0; q < 8; q++) { mp = fminf(mp, w_min[q]); mn = fmaxf(mn, w_max[q]); c += w_cnt[q]; }

    const bool valid = (c > 1) && (mp < INF) && (mn > -INF) && (mn > mp - 0.1f);
    if (!valid) {
        if (t == 0) g_rowloss[r] = 0.0f;
        return;
    }

    float psum = 0.f, nsum = 0.f;
    if (use_smem) {
        for (int j = t; j < Mpad; j += 256) {
            const float s = ss[j];
            if (!se[j]) {
                if (s + 0.1f > mp) nsum += __expf(40.0f * (s - 0.5f));
            } else if (s < C1 && s - 0.1f < mn) {
                psum += __expf(-2.0f * (s - 0.5f));
            }
        }
    } else {
        const float* __restrict__ row = (const float*)row4;
        for (int j = t; j < M; j += 256) {
            const float s = (j == r) ? 1.0f : __ldg(row + j);
            const bool eq = (__ldg(&g_lab[j]) == labr);
            if (!eq) {
                if (s + 0.1f > mp) nsum += __expf(40.0f * (s - 0.5f));
            } else if (s < C1 && s - 0.1f < mn) {
                psum += __expf(-2.0f * (s - 0.5f));
            }
        }
    }
#pragma unroll
    for (int o = 16; o; o >>= 1) {
        psum += __shfl_xor_sync(0xffffffffu, psum, o);
        nsum += __shfl_xor_sync(0xffffffffu, nsum, o);
    }
    if (lane == 0) { w_p[w] = psum; w_n[w] = nsum; }
    __syncthreads();
    if (t == 0) {
        float P = 0.f, N = 0.f;
#pragma unroll
        for (int q = 0; q < 8; q++) { P += w_p[q]; N += w_n[q]; }
        g_rowloss[r] = log1pf(P) / 2.0f + log1pf(N) / 40.0f;
    }
}

// ---------------- kernel 4: deterministic final sum --------------------------
__global__ void __launch_bounds__(256)
k_finalize(float* __restrict__ out)
{
    const int M = g_M;
    const int t = threadIdx.x;
    float acc = 0.f;
    for (int i = t; i < M; i += 256) acc += g_rowloss[i];
    __shared__ float red[256];
    red[t] = acc;
    __syncthreads();
    for (int off = 128; off > 0; off >>= 1) {
        if (t < off) red[t] += red[t + off];
        __syncthreads();
    }
    if (t == 0) out[0] = red[0] / (float)B_ROWS;
}

// ---------------- launcher ---------------------------------------------------
extern "C" void kernel_launch(void* const* d_in, const int* in_sizes, int n_in,
                              void* d_out, int out_size)
{
    const float* feats  = (const float*)d_in[0];
    const void*  labels = d_in[1];
    const float* score  = (const float*)d_in[2];
    const int*   tidx   = (const int*)d_in[3];
    float* out = (float*)d_out;

    cudaFuncSetAttribute(k_gemm, cudaFuncAttributeMaxDynamicSharedMemorySize, GEMM_SMEM);

    k_select<<<1, NTHREADS_SCAN>>>(score, labels, tidx);
    k_normalize<<<B_ROWS, 256>>>(feats);
    dim3 grid(B_ROWS / TILE, B_ROWS / TILE);
    k_gemm<<<grid, 256, GEMM_SMEM>>>();
    k_rowloss<<<B_ROWS, 256>>>();
    k_finalize<<<1, 256>>>(out);
}